// round 1
// baseline (speedup 1.0000x reference)
#include <cuda_runtime.h>
#include <math.h>

#define NS        100
#define NPIX      (NS * NS)          // 10000
#define NQUAD     (NPIX / 4)         // 2500
#define PARTS     8
#define MAXPARTS  16
#define BLOCK     256
#define INF_F     1000000000.0f
#define MU_F      1e-8f
#define SAFE_THR  0.05f

__global__ __launch_bounds__(BLOCK)
void physical_circle_kernel(const float* __restrict__ seg_maps,      // (B,100,100)
                            const float* __restrict__ seg_map_paras, // (B,6) W0 W1 b0 b1 order0 0
                            const float* __restrict__ trajectories,  // (B,8,2)
                            const float* __restrict__ current_pos,   // (B,1,2)
                            float* __restrict__ out)                 // (B,16,3)
{
    const int b   = blockIdx.x;
    const int tid = threadIdx.x;

    __shared__ float sp[8];      // invW0, invW1, offI, offJ, r2, ml, swapflag
    __shared__ int   smin[PARTS];

    if (tid < PARTS) smin[tid] = __float_as_int(INF_F);
    if (tid == 0) {
        const float* pr = seg_map_paras + b * 6;
        float W0 = pr[0], W1 = pr[1], b0 = pr[2], b1 = pr[3], order0 = pr[4];
        bool swap = (order0 == 1.0f);

        const float* tr = trajectories + b * 16;
        float mvx = tr[14] - tr[0];
        float mvy = tr[15] - tr[1];
        float ml  = sqrtf(mvx * mvx + mvy * mvy);
        float r   = 2.0f * ml;

        float cx = current_pos[b * 2 + 0];
        float cy = current_pos[b * 2 + 1];

        float invW0 = 1.0f / W0;
        float invW1 = 1.0f / W1;
        // dirI = (i - b0)/W0 - (swap ? cy : cx)  = fmaf(i, invW0, offI)
        // dirJ = (j - b1)/W1 - (swap ? cx : cy)  = fmaf(j, invW1, offJ)
        float offI = -b0 * invW0 - (swap ? cy : cx);
        float offJ = -b1 * invW1 - (swap ? cx : cy);

        sp[0] = invW0; sp[1] = invW1; sp[2] = offI; sp[3] = offJ;
        sp[4] = r * r; sp[5] = ml;    sp[6] = swap ? 1.0f : 0.0f;
    }
    __syncthreads();

    const float invW0 = sp[0], invW1 = sp[1], offI = sp[2], offJ = sp[3];
    const float r2 = sp[4], ml = sp[5];
    const bool  swp = (sp[6] != 0.0f);

    float lmin[PARTS];
#pragma unroll
    for (int p = 0; p < PARTS; ++p) lmin[p] = INF_F;

    const float4* mp4 = (const float4*)(seg_maps + (size_t)b * NPIX);

    for (int v = tid; v < NQUAD; v += BLOCK) {
        float4 m4 = mp4[v];
        int k = v * 4;
        int i = k / NS;            // one row per quad (100 % 4 == 0)
        int j = k - i * NS;

        float dirI  = fmaf((float)i, invW0, offI);
        float dirI2 = dirI * dirI;

        float mv[4] = { m4.x, m4.y, m4.z, m4.w };
#pragma unroll
        for (int c4 = 0; c4 < 4; ++c4) {
            float m    = mv[c4];
            float dirJ = fmaf((float)(j + c4), invW1, offJ);
            float dd   = fmaf(dirJ, dirJ, dirI2);
            if (m > SAFE_THR && dd <= r2) {
                float dist = sqrtf(dd);
                float eq   = (dist + MU_F) / (m + MU_F);
                float s = swp ? dirJ : dirI;   // angle = atan2(s, c)
                float c = swp ? dirI : dirJ;
                // octant of atan2(s,c) mod 2pi in sectors of pi/4
                int bin;
                if (s >= 0.0f) {
                    if (c >= 0.0f) bin = (s <= c)  ? 0 : 1;
                    else           bin = (s >= -c) ? 2 : 3;
                } else {
                    if (c <= 0.0f) bin = (-s <= -c) ? 4 : 5;
                    else           bin = (-s >= c)  ? 6 : 7;
                }
#pragma unroll
                for (int p = 0; p < PARTS; ++p)
                    lmin[p] = (bin == p) ? fminf(lmin[p], eq) : lmin[p];
            }
        }
    }

    // warp-level min reduce, then one shared atomic per warp per bin
#pragma unroll
    for (int p = 0; p < PARTS; ++p) {
        float v = lmin[p];
#pragma unroll
        for (int o = 16; o > 0; o >>= 1)
            v = fminf(v, __shfl_xor_sync(0xffffffffu, v, o));
        if ((tid & 31) == 0)
            atomicMin(&smin[p], __float_as_int(v));  // all values >= 0: int order == float order
    }
    __syncthreads();

    if (tid < MAXPARTS) {
        float fv = 0.0f, fd = 0.0f, fr = 0.0f;
        if (tid < PARTS) {
            float md = fminf(__int_as_float(smin[tid]), INF_F);
            if (md < INF_F) {
                fv = ml;
                fd = md;
                fr = (float)(6.283185307179586 * ((double)tid + 0.5) / 8.0);
            }
        }
        float* o = out + (size_t)b * (MAXPARTS * 3) + tid * 3;
        o[0] = fv; o[1] = fd; o[2] = fr;
    }
}

extern "C" void kernel_launch(void* const* d_in, const int* in_sizes, int n_in,
                              void* d_out, int out_size)
{
    const float* seg_maps      = (const float*)d_in[0];
    const float* seg_map_paras = (const float*)d_in[1];
    const float* trajectories  = (const float*)d_in[2];
    const float* current_pos   = (const float*)d_in[3];
    float* out = (float*)d_out;

    int B = in_sizes[0] / NPIX;   // 1024
    physical_circle_kernel<<<B, BLOCK>>>(seg_maps, seg_map_paras, trajectories,
                                         current_pos, out);
}